// round 3
// baseline (speedup 1.0000x reference)
#include <cuda_runtime.h>

#define NN 100000
#define EE 1600000
#define F  128

// ---- static device scratch (no allocation allowed) ----
__device__ float g_h[(size_t)NN * F];     // x @ W
__device__ float g_deg[NN];               // degree, then dinv
__device__ int   g_count[NN];
__device__ int   g_cursor[NN];
__device__ int   g_offsets[NN + 1];
__device__ int   g_srcs[EE];              // CSR by dst: src indices
__device__ float g_wts[EE];               // CSR by dst: edge weights
__device__ int   g_bsums[128];            // block sums for scan

// ---------------------------------------------------------------------------
__global__ void k_init(int n) {
    int i = blockIdx.x * blockDim.x + threadIdx.x;
    if (i < n) { g_deg[i] = 1.0f; g_count[i] = 0; g_cursor[i] = 0; }
}

__global__ void k_hist(const int* __restrict__ dst, const float* __restrict__ w, int e) {
    int i = blockIdx.x * blockDim.x + threadIdx.x;
    if (i < e) {
        int d = dst[i];
        atomicAdd(&g_deg[d], w[i]);
        atomicAdd(&g_count[d], 1);
    }
}

// per-1024 block exclusive scan of g_count -> g_offsets, block totals -> g_bsums
__global__ void k_scan1(int n) {
    __shared__ int s[1024];
    int t = threadIdx.x;
    int i = blockIdx.x * 1024 + t;
    int c = (i < n) ? g_count[i] : 0;
    s[t] = c;
    __syncthreads();
    for (int off = 1; off < 1024; off <<= 1) {
        int v = 0;
        if (t >= off) v = s[t - off];
        __syncthreads();
        s[t] += v;
        __syncthreads();
    }
    int incl = s[t];
    if (i < n) g_offsets[i] = incl - c;           // exclusive within block
    if (t == 1023) g_bsums[blockIdx.x] = incl;    // block total
}

// exclusive scan of block sums (nb <= 128)
__global__ void k_scan2(int nb) {
    __shared__ int s[128];
    int t = threadIdx.x;
    int v = (t < nb) ? g_bsums[t] : 0;
    s[t] = v;
    __syncthreads();
    for (int off = 1; off < 128; off <<= 1) {
        int u = 0;
        if (t >= off) u = s[t - off];
        __syncthreads();
        s[t] += u;
        __syncthreads();
    }
    if (t < nb) g_bsums[t] = s[t] - v;            // exclusive
}

// add block bases, finalize dinv, set offsets[n]
__global__ void k_finish(int n, int e) {
    int i = blockIdx.x * blockDim.x + threadIdx.x;
    if (i < n) {
        g_offsets[i] += g_bsums[i >> 10];
        g_deg[i] = rsqrtf(g_deg[i]);              // deg >= 1 (self loop weight 1)
    }
    if (i == 0) g_offsets[n] = e;
}

__global__ void k_scatter(const int* __restrict__ src, const int* __restrict__ dst,
                          const float* __restrict__ w, int e) {
    int i = blockIdx.x * blockDim.x + threadIdx.x;
    if (i < e) {
        int d = dst[i];
        int p = g_offsets[d] + atomicAdd(&g_cursor[d], 1);
        g_srcs[p] = src[i];
        g_wts[p]  = w[i];
    }
}

// ---------------------------------------------------------------------------
// h = x @ W   (x: [n,128] row-major, W: [128,128] row-major)
// block: 256 threads, tile 128 rows x 128 cols, 8x8 per thread, k-tiles of 32
__global__ void k_gemm(const float* __restrict__ x, const float* __restrict__ Wm, int n) {
    __shared__ __align__(16) float Xs[32][132];   // [k][row], padded
    __shared__ __align__(16) float Ws[32][128];   // [k][col]
    int tid  = threadIdx.x;
    int row0 = blockIdx.x * 128;
    int tr = (tid >> 4) << 3;                     // 0..120 (row base)
    int tc = (tid & 15) << 3;                     // 0..120 (col base)
    float acc[8][8];
    #pragma unroll
    for (int i = 0; i < 8; i++)
        #pragma unroll
        for (int j = 0; j < 8; j++) acc[i][j] = 0.f;

    int lrow = tid >> 3;                          // 0..31
    int lk   = (tid & 7) << 2;                    // 0,4,...,28
    for (int k0 = 0; k0 < F; k0 += 32) {
        #pragma unroll
        for (int rr = 0; rr < 4; ++rr) {
            int row = lrow + rr * 32;
            int gr  = row0 + row;
            float4 v = make_float4(0.f, 0.f, 0.f, 0.f);
            if (gr < n) v = *(const float4*)(x + (size_t)gr * F + k0 + lk);
            Xs[lk + 0][row] = v.x; Xs[lk + 1][row] = v.y;
            Xs[lk + 2][row] = v.z; Xs[lk + 3][row] = v.w;
        }
        #pragma unroll
        for (int cc = 0; cc < 4; ++cc) {
            *(float4*)&Ws[lrow][lk + cc * 32] =
                *(const float4*)(Wm + (size_t)(k0 + lrow) * F + lk + cc * 32);
        }
        __syncthreads();
        #pragma unroll
        for (int k = 0; k < 32; k++) {
            float a[8], bw[8];
            *(float4*)&a[0]  = *(float4*)&Xs[k][tr];
            *(float4*)&a[4]  = *(float4*)&Xs[k][tr + 4];
            *(float4*)&bw[0] = *(float4*)&Ws[k][tc];
            *(float4*)&bw[4] = *(float4*)&Ws[k][tc + 4];
            #pragma unroll
            for (int i = 0; i < 8; i++)
                #pragma unroll
                for (int j = 0; j < 8; j++)
                    acc[i][j] = fmaf(a[i], bw[j], acc[i][j]);
        }
        __syncthreads();
    }
    #pragma unroll
    for (int i = 0; i < 8; i++) {
        int gr = row0 + tr + i;
        if (gr < n) {
            float* hp = g_h + (size_t)gr * F + tc;
            *(float4*)hp       = make_float4(acc[i][0], acc[i][1], acc[i][2], acc[i][3]);
            *((float4*)hp + 1) = make_float4(acc[i][4], acc[i][5], acc[i][6], acc[i][7]);
        }
    }
}

// ---------------------------------------------------------------------------
// one warp per dst node: emb = sum_nbr norm * h[src] + dinv^2 * h[node] + b
__global__ void k_agg(const float* __restrict__ b, float* __restrict__ out,
                      int n, int write_relu) {
    int node = (blockIdx.x * blockDim.x + threadIdx.x) >> 5;
    int lane = threadIdx.x & 31;
    if (node >= n) return;

    float di = g_deg[node];                       // dinv[node]
    float4 bb = *(const float4*)(b + lane * 4);
    float4 hs = *(const float4*)(g_h + (size_t)node * F + lane * 4);
    float sn = di * di;                           // self-loop norm
    float4 acc;
    acc.x = fmaf(hs.x, sn, bb.x);
    acc.y = fmaf(hs.y, sn, bb.y);
    acc.z = fmaf(hs.z, sn, bb.z);
    acc.w = fmaf(hs.w, sn, bb.w);

    int s = g_offsets[node];
    int e = g_offsets[node + 1];
    for (int p = s; p < e; ++p) {
        int   src = g_srcs[p];                    // same addr all lanes -> broadcast
        float nrm = g_deg[src] * g_wts[p] * di;
        float4 hv = *(const float4*)(g_h + (size_t)src * F + lane * 4);
        acc.x = fmaf(hv.x, nrm, acc.x);
        acc.y = fmaf(hv.y, nrm, acc.y);
        acc.z = fmaf(hv.z, nrm, acc.z);
        acc.w = fmaf(hv.w, nrm, acc.w);
    }

    *(float4*)(out + (size_t)node * F + lane * 4) = acc;
    if (write_relu) {
        float4 r = make_float4(fmaxf(acc.x, 0.f), fmaxf(acc.y, 0.f),
                               fmaxf(acc.z, 0.f), fmaxf(acc.w, 0.f));
        *(float4*)(out + (size_t)n * F + (size_t)node * F + lane * 4) = r;
    }
}

// ---------------------------------------------------------------------------
extern "C" void kernel_launch(void* const* d_in, const int* in_sizes, int n_in,
                              void* d_out, int out_size) {
    const float* x  = (const float*)d_in[0];      // [n, 128]
    const float* W  = (const float*)d_in[1];      // [128, 128]
    const float* b  = (const float*)d_in[2];      // [128]
    // d_in[3] = level (unused, always 0)
    const int*   ei = (const int*)d_in[4];        // [2, e]
    const float* ew = (const float*)d_in[5];      // [e]

    int n = in_sizes[0] / F;
    int e = in_sizes[4] / 2;
    if (n > NN) n = NN;
    if (e > EE) e = EE;
    const int* src = ei;
    const int* dst = ei + e;
    float* out = (float*)d_out;
    int write_relu = (out_size >= 2 * n * F) ? 1 : 0;

    int nb = (n + 1023) / 1024;

    k_init   <<<(n + 255) / 256, 256>>>(n);
    k_hist   <<<(e + 255) / 256, 256>>>(dst, ew, e);
    k_scan1  <<<nb, 1024>>>(n);
    k_scan2  <<<1, 128>>>(nb);
    k_finish <<<(n + 255) / 256, 256>>>(n, e);
    k_scatter<<<(e + 255) / 256, 256>>>(src, dst, ew, e);
    k_gemm   <<<(n + 127) / 128, 256>>>(x, W, n);
    k_agg    <<<(n * 32 + 255) / 256, 256>>>(b, out, n, write_relu);
}

// round 4
// speedup vs baseline: 1.0299x; 1.0299x over previous
#include <cuda_runtime.h>

#define NN 100000
#define EE 1600000
#define F  128

// ---- static device scratch (no allocation allowed) ----
__device__ float g_h[(size_t)NN * F];     // x @ W
__device__ float g_dinv[NN];              // rsqrt(weighted degree)
__device__ int   g_count[NN];
__device__ int   g_pos[NN];               // scatter cursors (init = offsets)
__device__ int   g_offsets[NN + 1];
__device__ int2  g_edge[EE];              // CSR by dst: {src, bitcast(w)}
__device__ int   g_bsums[128];            // block sums for scan

// ---------------------------------------------------------------------------
__global__ void k_init(int n) {
    int i = blockIdx.x * blockDim.x + threadIdx.x;
    if (i < n) g_count[i] = 0;
}

__global__ void k_hist(const int* __restrict__ dst, int e) {
    int i = blockIdx.x * blockDim.x + threadIdx.x;
    if (i < e) atomicAdd(&g_count[dst[i]], 1);   // no return use -> RED
}

// per-1024 block exclusive scan of g_count -> g_offsets, block totals -> g_bsums
__global__ void k_scan1(int n) {
    __shared__ int s[1024];
    int t = threadIdx.x;
    int i = blockIdx.x * 1024 + t;
    int c = (i < n) ? g_count[i] : 0;
    s[t] = c;
    __syncthreads();
    for (int off = 1; off < 1024; off <<= 1) {
        int v = 0;
        if (t >= off) v = s[t - off];
        __syncthreads();
        s[t] += v;
        __syncthreads();
    }
    int incl = s[t];
    if (i < n) g_offsets[i] = incl - c;           // exclusive within block
    if (t == 1023) g_bsums[blockIdx.x] = incl;    // block total
}

// exclusive scan of block sums (nb <= 128)
__global__ void k_scan2(int nb) {
    __shared__ int s[128];
    int t = threadIdx.x;
    int v = (t < nb) ? g_bsums[t] : 0;
    s[t] = v;
    __syncthreads();
    for (int off = 1; off < 128; off <<= 1) {
        int u = 0;
        if (t >= off) u = s[t - off];
        __syncthreads();
        s[t] += u;
        __syncthreads();
    }
    if (t < nb) g_bsums[t] = s[t] - v;            // exclusive
}

// add block bases, copy to scatter cursors, set offsets[n]
__global__ void k_finish(int n, int e) {
    int i = blockIdx.x * blockDim.x + threadIdx.x;
    if (i < n) {
        int o = g_offsets[i] + g_bsums[i >> 10];
        g_offsets[i] = o;
        g_pos[i] = o;
    }
    if (i == 0) g_offsets[n] = e;
}

__global__ void k_scatter(const int* __restrict__ src, const int* __restrict__ dst,
                          const float* __restrict__ w, int e) {
    int i = blockIdx.x * blockDim.x + threadIdx.x;
    if (i < e) {
        int d = dst[i];
        int p = atomicAdd(&g_pos[d], 1);
        g_edge[p] = make_int2(src[i], __float_as_int(w[i]));
    }
}

// weighted degree from CSR (no atomics): warp per node, then dinv
__global__ void k_deg(int n) {
    int node = (blockIdx.x * blockDim.x + threadIdx.x) >> 5;
    int lane = threadIdx.x & 31;
    if (node >= n) return;
    int s0 = g_offsets[node];
    int e0 = g_offsets[node + 1];
    float sum = 0.f;
    for (int p = s0 + lane; p < e0; p += 32)
        sum += __int_as_float(g_edge[p].y);
    #pragma unroll
    for (int off = 16; off > 0; off >>= 1)
        sum += __shfl_xor_sync(0xffffffffu, sum, off);
    if (lane == 0) g_dinv[node] = rsqrtf(sum + 1.0f);   // +1 self loop
}

// ---------------------------------------------------------------------------
// h = x @ W   (x: [n,128] row-major, W: [128,128] row-major)
// block: 256 threads, tile 128 rows x 128 cols, 8x8 per thread, k-tiles of 32
__global__ void k_gemm(const float* __restrict__ x, const float* __restrict__ Wm, int n) {
    __shared__ __align__(16) float Xs[32][132];   // [k][row], padded
    __shared__ __align__(16) float Ws[32][128];   // [k][col]
    int tid  = threadIdx.x;
    int row0 = blockIdx.x * 128;
    int tr = (tid >> 4) << 3;                     // 0..120 (row base)
    int tc = (tid & 15) << 3;                     // 0..120 (col base)
    float acc[8][8];
    #pragma unroll
    for (int i = 0; i < 8; i++)
        #pragma unroll
        for (int j = 0; j < 8; j++) acc[i][j] = 0.f;

    int lrow = tid >> 3;                          // 0..31
    int lk   = (tid & 7) << 2;                    // 0,4,...,28
    for (int k0 = 0; k0 < F; k0 += 32) {
        #pragma unroll
        for (int rr = 0; rr < 4; ++rr) {
            int row = lrow + rr * 32;
            int gr  = row0 + row;
            float4 v = make_float4(0.f, 0.f, 0.f, 0.f);
            if (gr < n) v = *(const float4*)(x + (size_t)gr * F + k0 + lk);
            Xs[lk + 0][row] = v.x; Xs[lk + 1][row] = v.y;
            Xs[lk + 2][row] = v.z; Xs[lk + 3][row] = v.w;
        }
        #pragma unroll
        for (int cc = 0; cc < 4; ++cc) {
            *(float4*)&Ws[lrow][lk + cc * 32] =
                *(const float4*)(Wm + (size_t)(k0 + lrow) * F + lk + cc * 32);
        }
        __syncthreads();
        #pragma unroll
        for (int k = 0; k < 32; k++) {
            float a[8], bw[8];
            *(float4*)&a[0]  = *(float4*)&Xs[k][tr];
            *(float4*)&a[4]  = *(float4*)&Xs[k][tr + 4];
            *(float4*)&bw[0] = *(float4*)&Ws[k][tc];
            *(float4*)&bw[4] = *(float4*)&Ws[k][tc + 4];
            #pragma unroll
            for (int i = 0; i < 8; i++)
                #pragma unroll
                for (int j = 0; j < 8; j++)
                    acc[i][j] = fmaf(a[i], bw[j], acc[i][j]);
        }
        __syncthreads();
    }
    #pragma unroll
    for (int i = 0; i < 8; i++) {
        int gr = row0 + tr + i;
        if (gr < n) {
            float* hp = g_h + (size_t)gr * F + tc;
            *(float4*)hp       = make_float4(acc[i][0], acc[i][1], acc[i][2], acc[i][3]);
            *((float4*)hp + 1) = make_float4(acc[i][4], acc[i][5], acc[i][6], acc[i][7]);
        }
    }
}

// ---------------------------------------------------------------------------
// one warp per dst node: emb = sum_nbr norm * h[src] + dinv^2 * h[node] + b
__global__ void k_agg(const float* __restrict__ b, float* __restrict__ out,
                      int n, int write_relu) {
    int node = (blockIdx.x * blockDim.x + threadIdx.x) >> 5;
    int lane = threadIdx.x & 31;
    if (node >= n) return;

    float di = g_dinv[node];
    float4 bb = *(const float4*)(b + lane * 4);
    float4 hs = *(const float4*)(g_h + (size_t)node * F + lane * 4);
    float sn = di * di;                           // self-loop norm
    float4 acc;
    acc.x = fmaf(hs.x, sn, bb.x);
    acc.y = fmaf(hs.y, sn, bb.y);
    acc.z = fmaf(hs.z, sn, bb.z);
    acc.w = fmaf(hs.w, sn, bb.w);

    int s = g_offsets[node];
    int e = g_offsets[node + 1];
    int p = s;
    // 2-edge software pipeline: doubles outstanding loads per iteration
    for (; p + 2 <= e; p += 2) {
        int2 e0 = g_edge[p];
        int2 e1 = g_edge[p + 1];
        float d0 = g_dinv[e0.x];
        float d1 = g_dinv[e1.x];
        const float4 h0 = *(const float4*)(g_h + (size_t)e0.x * F + lane * 4);
        const float4 h1 = *(const float4*)(g_h + (size_t)e1.x * F + lane * 4);
        float n0 = d0 * __int_as_float(e0.y) * di;
        float n1 = d1 * __int_as_float(e1.y) * di;
        acc.x = fmaf(h0.x, n0, acc.x); acc.y = fmaf(h0.y, n0, acc.y);
        acc.z = fmaf(h0.z, n0, acc.z); acc.w = fmaf(h0.w, n0, acc.w);
        acc.x = fmaf(h1.x, n1, acc.x); acc.y = fmaf(h1.y, n1, acc.y);
        acc.z = fmaf(h1.z, n1, acc.z); acc.w = fmaf(h1.w, n1, acc.w);
    }
    if (p < e) {
        int2 e0 = g_edge[p];
        float nrm = g_dinv[e0.x] * __int_as_float(e0.y) * di;
        const float4 hv = *(const float4*)(g_h + (size_t)e0.x * F + lane * 4);
        acc.x = fmaf(hv.x, nrm, acc.x); acc.y = fmaf(hv.y, nrm, acc.y);
        acc.z = fmaf(hv.z, nrm, acc.z); acc.w = fmaf(hv.w, nrm, acc.w);
    }

    *(float4*)(out + (size_t)node * F + lane * 4) = acc;
    if (write_relu) {
        float4 r = make_float4(fmaxf(acc.x, 0.f), fmaxf(acc.y, 0.f),
                               fmaxf(acc.z, 0.f), fmaxf(acc.w, 0.f));
        *(float4*)(out + (size_t)n * F + (size_t)node * F + lane * 4) = r;
    }
}

// ---------------------------------------------------------------------------
extern "C" void kernel_launch(void* const* d_in, const int* in_sizes, int n_in,
                              void* d_out, int out_size) {
    const float* x  = (const float*)d_in[0];      // [n, 128]
    const float* W  = (const float*)d_in[1];      // [128, 128]
    const float* b  = (const float*)d_in[2];      // [128]
    // d_in[3] = level (unused, always 0)
    const int*   ei = (const int*)d_in[4];        // [2, e]
    const float* ew = (const float*)d_in[5];      // [e]

    int n = in_sizes[0] / F;
    int e = in_sizes[4] / 2;
    if (n > NN) n = NN;
    if (e > EE) e = EE;
    const int* src = ei;
    const int* dst = ei + e;
    float* out = (float*)d_out;
    int write_relu = (out_size >= 2 * n * F) ? 1 : 0;

    int nb = (n + 1023) / 1024;

    // one-time side stream + events (resource init only; per-call work is
    // identical and deterministic). Created on the first (non-captured)
    // correctness call; subsequent captured calls only record/wait.
    static int init_done = 0;
    static int use_fork = 0;
    static cudaStream_t s_side;
    static cudaEvent_t ev_fork, ev_join;
    if (!init_done) {
        init_done = 1;
        if (cudaStreamCreateWithFlags(&s_side, cudaStreamNonBlocking) == cudaSuccess &&
            cudaEventCreateWithFlags(&ev_fork, cudaEventDisableTiming) == cudaSuccess &&
            cudaEventCreateWithFlags(&ev_join, cudaEventDisableTiming) == cudaSuccess)
            use_fork = 1;
    }

    if (use_fork) {
        // fork: GEMM runs on the side stream, overlapped with the CSR build
        cudaEventRecord(ev_fork, 0);
        cudaStreamWaitEvent(s_side, ev_fork, 0);
        k_gemm<<<(n + 127) / 128, 256, 0, s_side>>>(x, W, n);
        cudaEventRecord(ev_join, s_side);
    }

    k_init   <<<(n + 255) / 256, 256>>>(n);
    k_hist   <<<(e + 255) / 256, 256>>>(dst, e);
    k_scan1  <<<nb, 1024>>>(n);
    k_scan2  <<<1, 128>>>(nb);
    k_finish <<<(n + 255) / 256, 256>>>(n, e);
    k_scatter<<<(e + 255) / 256, 256>>>(src, dst, ew, e);
    k_deg    <<<(n * 32 + 255) / 256, 256>>>(n);

    if (use_fork) {
        cudaStreamWaitEvent(0, ev_join, 0);       // join before aggregation
    } else {
        k_gemm<<<(n + 127) / 128, 256>>>(x, W, n);
    }

    k_agg<<<(n * 32 + 255) / 256, 256>>>(b, out, n, write_relu);
}